// round 8
// baseline (speedup 1.0000x reference)
#include <cuda_runtime.h>
#include <cuda_bf16.h>
#include <cstdint>

#define TOKENS 32768
#define DMODEL 4096
#define NEXP   64
#define BM     128
#define KS     32                 // k-slab per stage
#define NSLAB  (DMODEL / KS)      // 128
#define NBLK_B (TOKENS / 256)     // 128 blocks in the gate kernel
#define MAXR   1024               // rescue list capacity
#define EPS_MARGIN 6e-3f          // rescue threshold on noisy top1-top2 margin

// Scratch (no allocations allowed)
__device__ float g_h[TOKENS * NEXP];
__device__ float g_imp[NBLK_B * NEXP];
__device__ int   g_load[NBLK_B * NEXP];
__device__ __align__(16) __nv_bfloat16 g_w1b[2][NEXP * DMODEL];  // w1 bf16 2-splits
__device__ int g_rescue_cnt;
__device__ int g_rescue_list[MAXR];
__device__ int g_load_delta[NEXP];

// ---------------- helpers ----------------
static __device__ __forceinline__ uint32_t smem_u32(const void* p) {
    uint32_t a;
    asm("{ .reg .u64 t; cvta.to.shared.u64 t, %1; cvt.u32.u64 %0, t; }" : "=r"(a) : "l"(p));
    return a;
}
// packed cvt: result = {lo=bf16(a), hi=bf16(b)}
static __device__ __forceinline__ uint32_t cvt2(float a, float b) {
    uint32_t r;
    asm("cvt.rn.bf16x2.f32 %0, %1, %2;" : "=r"(r) : "f"(b), "f"(a));
    return r;
}
static __device__ __forceinline__ float lo_f(uint32_t p) { return __uint_as_float(p << 16); }
static __device__ __forceinline__ float hi_f(uint32_t p) { return __uint_as_float(p & 0xFFFF0000u); }

static __device__ __forceinline__ void ldsm4(uint32_t (&r)[4], uint32_t addr) {
    asm volatile("ldmatrix.sync.aligned.m8n8.x4.shared.b16 {%0,%1,%2,%3}, [%4];"
        : "=r"(r[0]), "=r"(r[1]), "=r"(r[2]), "=r"(r[3]) : "r"(addr));
}
static __device__ __forceinline__ void mma16816(float (&c)[4], const uint32_t (&a)[4],
                                                uint32_t b0, uint32_t b1) {
    asm volatile("mma.sync.aligned.m16n8k16.row.col.f32.bf16.bf16.f32 "
        "{%0,%1,%2,%3}, {%4,%5,%6,%7}, {%8,%9}, {%0,%1,%2,%3};"
        : "+f"(c[0]), "+f"(c[1]), "+f"(c[2]), "+f"(c[3])
        : "r"(a[0]), "r"(a[1]), "r"(a[2]), "r"(a[3]), "r"(b0), "r"(b1));
}

// ============================================================================
// w1 pre-split: fp32 -> 2 bf16 matrices. Also resets rescue state (runs first
// every replay).
// ============================================================================
__global__ void w1_split_kernel(const float* __restrict__ w1) {
    if (blockIdx.x == 0) {
        if (threadIdx.x == 0) g_rescue_cnt = 0;
        if (threadIdx.x < NEXP) g_load_delta[threadIdx.x] = 0;
    }
    int base = (blockIdx.x * 256 + threadIdx.x) * 4;
    float4 v = *reinterpret_cast<const float4*>(&w1[base]);
    uint32_t p0a = cvt2(v.x, v.y), p0b = cvt2(v.z, v.w);
    float r0 = v.x - lo_f(p0a), r1 = v.y - hi_f(p0a);
    float r2 = v.z - lo_f(p0b), r3 = v.w - hi_f(p0b);
    uint32_t p1a = cvt2(r0, r1), p1b = cvt2(r2, r3);
    *reinterpret_cast<uint2*>(&g_w1b[0][base]) = make_uint2(p0a, p0b);
    *reinterpret_cast<uint2*>(&g_w1b[1][base]) = make_uint2(p1a, p1b);
}

// ============================================================================
// GEMM1: h = tanh(x @ w1^T), bf16x3 emulation (products 00, 01, 10) on
// mma.sync HMMA. CTA: 128 tokens x 64 experts, 8 warps, warp tile 32x32.
// Residual argmax risk is covered by the fp64 rescue pass.
// ============================================================================
__global__ void __launch_bounds__(256, 2)
gemm1_tensor(const float* __restrict__ x) {
    __shared__ __align__(128) __nv_bfloat16 As[2][BM * KS];    // 2 x 8KB
    __shared__ __align__(128) __nv_bfloat16 Bs[2][NEXP * KS];  // 2 x 4KB

    const int tid  = threadIdx.x;
    const int lane = tid & 31;
    const int warp = tid >> 5;
    const int wm   = warp >> 1;
    const int wn   = warp & 1;
    const int bm   = blockIdx.x * BM;

    float acc[2][4][4];
#pragma unroll
    for (int mt = 0; mt < 2; mt++)
#pragma unroll
        for (int nt = 0; nt < 4; nt++)
#pragma unroll
            for (int i = 0; i < 4; i++) acc[mt][nt][i] = 0.f;

    int xrow[4], xc4[4];
#pragma unroll
    for (int i = 0; i < 4; i++) { int idx = tid + 256 * i; xrow[i] = idx >> 3; xc4[i] = idx & 7; }
    const int wrow = tid >> 2, wc = tid & 3;

    uint32_t a_off[4];
#pragma unroll
    for (int i = 0; i < 4; i++) {
        int chunk = xc4[i] >> 1;
        int sw = chunk ^ ((xrow[i] >> 1) & 3);
        a_off[i] = (uint32_t)(xrow[i] * 64 + sw * 16 + (xc4[i] & 1) * 8);
    }
    const uint32_t b_off = (uint32_t)(wrow * 64 + ((wc ^ ((wrow >> 1) & 3)) * 16));

    const uint32_t As_base[2] = { smem_u32(&As[0][0]), smem_u32(&As[1][0]) };
    const uint32_t Bs_base[2] = { smem_u32(&Bs[0][0]), smem_u32(&Bs[1][0]) };

    const int a_row[2] = { wm * 32 + 0 * 16 + ((lane >> 3) & 1) * 8 + (lane & 7),
                           wm * 32 + 1 * 16 + ((lane >> 3) & 1) * 8 + (lane & 7) };
    const int a_cadd = (lane >> 4);
    const int b_row[2] = { wn * 32 + 0 * 16 + ((lane >> 4) & 1) * 8 + (lane & 7),
                           wn * 32 + 1 * 16 + ((lane >> 4) & 1) * 8 + (lane & 7) };
    const int b_cadd = ((lane >> 3) & 1);

    float4 xr[4];
    uint4  wr[2];
#pragma unroll
    for (int i = 0; i < 4; i++)
        xr[i] = *reinterpret_cast<const float4*>(&x[(size_t)(bm + xrow[i]) * DMODEL + xc4[i] * 4]);
#pragma unroll
    for (int s = 0; s < 2; s++)
        wr[s] = *reinterpret_cast<const uint4*>(&g_w1b[s][(size_t)wrow * DMODEL + wc * 8]);

#pragma unroll 1
    for (int sl = 0; sl < NSLAB; sl++) {
        if (sl) __syncthreads();

#pragma unroll
        for (int i = 0; i < 4; i++) {
            float4 v = xr[i];
            uint32_t p0a = cvt2(v.x, v.y), p0b = cvt2(v.z, v.w);
            float r0 = v.x - lo_f(p0a), r1 = v.y - hi_f(p0a);
            float r2 = v.z - lo_f(p0b), r3 = v.w - hi_f(p0b);
            uint32_t p1a = cvt2(r0, r1), p1b = cvt2(r2, r3);
            *reinterpret_cast<uint2*>((char*)As[0] + a_off[i]) = make_uint2(p0a, p0b);
            *reinterpret_cast<uint2*>((char*)As[1] + a_off[i]) = make_uint2(p1a, p1b);
        }
#pragma unroll
        for (int s = 0; s < 2; s++)
            *reinterpret_cast<uint4*>((char*)Bs[s] + b_off) = wr[s];
        __syncthreads();

        if (sl + 1 < NSLAB) {
            const int kk = (sl + 1) * KS;
#pragma unroll
            for (int i = 0; i < 4; i++)
                xr[i] = *reinterpret_cast<const float4*>(
                    &x[(size_t)(bm + xrow[i]) * DMODEL + kk + xc4[i] * 4]);
#pragma unroll
            for (int s = 0; s < 2; s++)
                wr[s] = *reinterpret_cast<const uint4*>(
                    &g_w1b[s][(size_t)wrow * DMODEL + kk + wc * 8]);
        }

#pragma unroll
        for (int kc = 0; kc < 2; kc++) {
            uint32_t a[2][2][4], b[2][2][4];
#pragma unroll
            for (int s = 0; s < 2; s++) {
#pragma unroll
                for (int mt = 0; mt < 2; mt++) {
                    int c = kc * 2 + a_cadd;
                    int sw = c ^ ((a_row[mt] >> 1) & 3);
                    ldsm4(a[s][mt], As_base[s] + (uint32_t)(a_row[mt] * 64 + sw * 16));
                }
#pragma unroll
                for (int nb = 0; nb < 2; nb++) {
                    int c = kc * 2 + b_cadd;
                    int sw = c ^ ((b_row[nb] >> 1) & 3);
                    ldsm4(b[s][nb], Bs_base[s] + (uint32_t)(b_row[nb] * 64 + sw * 16));
                }
            }
#define PROD(SA, SB)                                                            \
            {                                                                   \
                _Pragma("unroll")                                               \
                for (int mt = 0; mt < 2; mt++) {                                \
                    mma16816(acc[mt][0], a[SA][mt], b[SB][0][0], b[SB][0][1]);  \
                    mma16816(acc[mt][1], a[SA][mt], b[SB][0][2], b[SB][0][3]);  \
                    mma16816(acc[mt][2], a[SA][mt], b[SB][1][0], b[SB][1][1]);  \
                    mma16816(acc[mt][3], a[SA][mt], b[SB][1][2], b[SB][1][3]);  \
                }                                                               \
            }
            PROD(0, 0)
            PROD(0, 1)
            PROD(1, 0)
#undef PROD
        }
    }

#pragma unroll
    for (int mt = 0; mt < 2; mt++) {
#pragma unroll
        for (int nt = 0; nt < 4; nt++) {
            const int r0  = bm + wm * 32 + mt * 16 + (lane >> 2);
            const int col = wn * 32 + nt * 8 + (lane & 3) * 2;
            *reinterpret_cast<float2*>(&g_h[(size_t)r0 * NEXP + col]) =
                make_float2(tanhf(acc[mt][nt][0]), tanhf(acc[mt][nt][1]));
            *reinterpret_cast<float2*>(&g_h[(size_t)(r0 + 8) * NEXP + col]) =
                make_float2(tanhf(acc[mt][nt][2]), tanhf(acc[mt][nt][3]));
        }
    }
}

// ============================================================================
// Kernel B: logits = h @ w2^T; softmax; argmax(logits+noise); top-2 margin
// flags near-ties for fp64 rescue; deterministic block partials.
// ============================================================================
__global__ void __launch_bounds__(256)
gate_kernel(const float* __restrict__ w2, const float* __restrict__ noise,
            float* __restrict__ out) {
    __shared__ float w2s[NEXP][NEXP];
    __shared__ float s_imp[8][NEXP];
    __shared__ int   s_load[NEXP];

    const int tid  = threadIdx.x;
    const int warp = tid >> 5;

    for (int i = tid; i < NEXP * NEXP; i += 256) w2s[i >> 6][i & 63] = w2[i];
    if (tid < NEXP) s_load[tid] = 0;
    __syncthreads();

    const int t = blockIdx.x * 256 + tid;

    float l[NEXP];
#pragma unroll
    for (int e = 0; e < NEXP; e++) l[e] = 0.f;

    const float4* hrow = reinterpret_cast<const float4*>(&g_h[(size_t)t * NEXP]);
#pragma unroll 2
    for (int j4 = 0; j4 < 16; j4++) {
        float4 hv = hrow[j4];
#pragma unroll
        for (int e = 0; e < NEXP; e++) {
            l[e] += hv.x * w2s[e][4 * j4 + 0] + hv.y * w2s[e][4 * j4 + 1] +
                    hv.z * w2s[e][4 * j4 + 2] + hv.w * w2s[e][4 * j4 + 3];
        }
    }

    float maxl = l[0];
#pragma unroll
    for (int e = 1; e < NEXP; e++) maxl = fmaxf(maxl, l[e]);

    // argmax of logits + gumbel noise, tracking top-2 for the rescue margin
    const float4* nrow = reinterpret_cast<const float4*>(&noise[(size_t)t * NEXP]);
    float best = -3.402823466e38f, second = -3.402823466e38f;
    int   bi   = 0;
#pragma unroll
    for (int e4 = 0; e4 < 16; e4++) {
        float4 nv = nrow[e4];
        float v;
#define STEP(COMP, OFF)                                                        \
        v = l[4 * e4 + OFF] + nv.COMP;                                         \
        if (v > best) { second = best; best = v; bi = 4 * e4 + OFF; }          \
        else if (v > second) { second = v; }
        STEP(x, 0) STEP(y, 1) STEP(z, 2) STEP(w, 3)
#undef STEP
    }
    if (best - second < EPS_MARGIN) {
        int idx = atomicAdd(&g_rescue_cnt, 1);
        if (idx < MAXR) g_rescue_list[idx] = t;
    }

    float Z = 0.f;
#pragma unroll
    for (int e = 0; e < NEXP; e++) Z += expf(l[e] - maxl);
    const float inv = 1.0f / Z;

#pragma unroll
    for (int e = 0; e < NEXP; e++) {
        float v = expf(l[e] - maxl) * inv;
        v += __shfl_xor_sync(0xffffffffu, v, 16);
        v += __shfl_xor_sync(0xffffffffu, v, 8);
        v += __shfl_xor_sync(0xffffffffu, v, 4);
        v += __shfl_xor_sync(0xffffffffu, v, 2);
        v += __shfl_xor_sync(0xffffffffu, v, 1);
        if ((tid & 31) == 0) s_imp[warp][e] = v;
    }

    atomicAdd(&s_load[bi], 1);

    out[t]          = (float)bi;
    out[TOKENS + t] = best;

    __syncthreads();
    if (tid < NEXP) {
        float s = 0.f;
#pragma unroll
        for (int w = 0; w < 8; w++) s += s_imp[w][tid];
        g_imp[blockIdx.x * NEXP + tid]  = s;
        g_load[blockIdx.x * NEXP + tid] = s_load[tid];
    }
}

// ============================================================================
// Rescue: recompute flagged tokens' full gate in fp64 straight from inputs
// (independent of all bf16 staging machinery). Patches indices/scores and
// accumulates integer load deltas. Fixed-order fp64 sums -> deterministic.
// ============================================================================
__global__ void __launch_bounds__(256)
rescue_kernel(const float* __restrict__ x, const float* __restrict__ w1,
              const float* __restrict__ w2, const float* __restrict__ noise,
              float* __restrict__ out) {
    int cnt = g_rescue_cnt;
    if (cnt > MAXR) cnt = MAXR;
    if ((int)blockIdx.x >= cnt) return;
    const int t   = g_rescue_list[blockIdx.x];
    const int tid = threadIdx.x;
    const int j   = tid >> 2;     // expert for layer-1 row
    const int q   = tid & 3;      // k-quarter

    __shared__ double pz[NEXP][4];
    __shared__ double hs[NEXP];
    __shared__ double lv[NEXP];

    const float* xr = x + (size_t)t * DMODEL;
    const float* wr = w1 + (size_t)j * DMODEL;
    double partial = 0.0;
    const int k0 = q * (DMODEL / 4);
#pragma unroll 4
    for (int k = k0; k < k0 + DMODEL / 4; k++)
        partial += (double)xr[k] * (double)wr[k];
    pz[j][q] = partial;
    __syncthreads();

    if (q == 0) {
        double z = ((pz[j][0] + pz[j][1]) + pz[j][2]) + pz[j][3];
        hs[j] = tanh(z);
    }
    __syncthreads();

    if (tid < NEXP) {
        double s = 0.0;
        for (int jj = 0; jj < NEXP; jj++) s += hs[jj] * (double)w2[tid * NEXP + jj];
        lv[tid] = s + (double)noise[(size_t)t * NEXP + tid];
    }
    __syncthreads();

    if (tid == 0) {
        double bv = lv[0];
        int bi = 0;
        for (int e = 1; e < NEXP; e++)
            if (lv[e] > bv) { bv = lv[e]; bi = e; }
        const int old = (int)out[t];
        if (old != bi) {
            atomicAdd(&g_load_delta[old], -1);
            atomicAdd(&g_load_delta[bi], 1);
            out[t] = (float)bi;
        }
        out[TOKENS + t] = (float)bv;
    }
}

// ============================================================================
// Kernel C: finalize (deterministic fixed-order reductions + rescue deltas)
// ============================================================================
__global__ void finalize_kernel(float* __restrict__ out) {
    __shared__ float red[NEXP];
    const int e = threadIdx.x;

    float s  = 0.f;
    int   ld = g_load_delta[e];
    for (int b = 0; b < NBLK_B; b++) {
        s  += g_imp[b * NEXP + e];
        ld += g_load[b * NEXP + e];
    }
    const float imp_mean  = s * (1.0f / TOKENS);
    const float load_mean = (float)ld * (1.0f / TOKENS);

    out[2 * TOKENS + 1 + e]        = load_mean;
    out[2 * TOKENS + 1 + NEXP + e] = imp_mean;

    red[e] = imp_mean * load_mean;
    __syncthreads();
    if (e == 0) {
        float a = 0.f;
        for (int i = 0; i < NEXP; i++) a += red[i];
        out[2 * TOKENS] = (float)NEXP * a * 0.1f;
    }
}

extern "C" void kernel_launch(void* const* d_in, const int* in_sizes, int n_in,
                              void* d_out, int out_size) {
    const float* x     = (const float*)d_in[0];
    const float* w1    = (const float*)d_in[1];
    const float* w2    = (const float*)d_in[2];
    const float* noise = (const float*)d_in[3];
    float* out = (float*)d_out;

    w1_split_kernel<<<NEXP * DMODEL / 1024, 256>>>(w1);
    gemm1_tensor<<<TOKENS / BM, 256>>>(x);
    gate_kernel<<<NBLK_B, 256>>>(w2, noise, out);
    rescue_kernel<<<MAXR, 256>>>(x, w1, w2, noise, out);
    finalize_kernel<<<1, NEXP>>>(out);
}

// round 11
// speedup vs baseline: 1.4020x; 1.4020x over previous
#include <cuda_runtime.h>
#include <cuda_bf16.h>
#include <cstdint>

#define TOKENS 32768
#define DMODEL 4096
#define NEXP   64
#define BM     128
#define BK     16
#define XPITCH 132               // xs row pitch (f32): 16B-aligned, 2-way STS max
#define WPITCH 68                // ws row pitch (f32)
#define NSLAB  (DMODEL / BK)     // 256
#define NBLK_B (TOKENS / 256)    // 128 blocks in the gate kernel
#define MAXR   256               // rescue list capacity
#define EPS_MARGIN 2e-4f         // rescue threshold on noisy top1-top2 margin

// Scratch (no allocations allowed)
__device__ float g_h[TOKENS * NEXP];
__device__ float g_imp[NBLK_B * NEXP];
__device__ int   g_load[NBLK_B * NEXP];
__device__ int   g_rescue_cnt;
__device__ int   g_rescue_list[MAXR];
__device__ int   g_load_delta[NEXP];

// ---- packed f32x2 helpers (FFMA2 — only reachable via PTX fma.rn.f32x2) ----
static __device__ __forceinline__ unsigned long long pack2(float lo, float hi) {
    unsigned long long r;
    asm("mov.b64 %0, {%1, %2};" : "=l"(r) : "f"(lo), "f"(hi));
    return r;
}
static __device__ __forceinline__ void unpack2(unsigned long long v, float& lo, float& hi) {
    asm("mov.b64 {%0, %1}, %2;" : "=f"(lo), "=f"(hi) : "l"(v));
}
static __device__ __forceinline__ void ffma2(unsigned long long& d,
                                             unsigned long long a,
                                             unsigned long long b) {
    asm("fma.rn.f32x2 %0, %1, %2, %0;" : "+l"(d) : "l"(a), "l"(b));
}

// ============================================================================
// Kernel A: h = tanh(x @ w1^T)   [32768,4096] x [64,4096]^T -> [32768,64]
// 128 threads/CTA, tile 128 tokens x 64 experts, per-thread 8 tok x 8 exp
// (32 independent FFMA2 per k). BK=16 slab, register-staged double buffer.
//   lane&15  -> token group (8 consecutive tokens)
//   warp*2 + (lane>>4) -> expert group (8 experts)
// ============================================================================
__global__ void __launch_bounds__(128, 4)
gemm1_tanh(const float* __restrict__ x, const float* __restrict__ w1) {
    __shared__ __align__(16) float xs[BK][XPITCH];   // xs[k][token]
    __shared__ __align__(16) float ws[BK][WPITCH];   // ws[k][expert]

    const int tid  = threadIdx.x;
    const int lane = tid & 31;
    const int warp = tid >> 5;
    const int bm   = blockIdx.x * BM;
    const int tg   = lane & 15;                 // token group
    const int e0   = (warp * 2 + (lane >> 4)) * 8;

    // rescue-state reset (gate runs strictly after gemm1 in stream order)
    if (blockIdx.x == 0) {
        if (tid == 0) g_rescue_cnt = 0;
        if (tid < NEXP) g_load_delta[tid] = 0;
    }

    unsigned long long acc[4][8];               // 4 token-pairs x 8 experts
#pragma unroll
    for (int p = 0; p < 4; p++)
#pragma unroll
        for (int e = 0; e < 8; e++) acc[p][e] = 0ull;

    // loader coords: x -> 4 float4/thread, w1 -> 2 float4/thread per slab
    const int lrow = tid >> 2;                  // 0..31
    const int lc4  = tid & 3;                   // k-chunk (4 floats)

    // ---- prologue: load slab 0 ----
    float4 xr[4], wr[2];
#pragma unroll
    for (int i = 0; i < 4; i++)
        xr[i] = *reinterpret_cast<const float4*>(&x[(size_t)(bm + lrow + 32 * i) * DMODEL + lc4 * 4]);
#pragma unroll
    for (int i = 0; i < 2; i++)
        wr[i] = *reinterpret_cast<const float4*>(&w1[(size_t)(lrow + 32 * i) * DMODEL + lc4 * 4]);

#pragma unroll 1
    for (int sl = 0; sl < NSLAB; sl++) {
        if (sl) __syncthreads();    // all warps done reading previous slab

        // transpose-store current slab
#pragma unroll
        for (int i = 0; i < 4; i++) {
            const int row = lrow + 32 * i;
            xs[lc4 * 4 + 0][row] = xr[i].x;
            xs[lc4 * 4 + 1][row] = xr[i].y;
            xs[lc4 * 4 + 2][row] = xr[i].z;
            xs[lc4 * 4 + 3][row] = xr[i].w;
        }
#pragma unroll
        for (int i = 0; i < 2; i++) {
            const int er = lrow + 32 * i;
            ws[lc4 * 4 + 0][er] = wr[i].x;
            ws[lc4 * 4 + 1][er] = wr[i].y;
            ws[lc4 * 4 + 2][er] = wr[i].z;
            ws[lc4 * 4 + 3][er] = wr[i].w;
        }
        __syncthreads();

        // prefetch next slab (overlaps compute below)
        if (sl + 1 < NSLAB) {
            const int kk = (sl + 1) * BK;
#pragma unroll
            for (int i = 0; i < 4; i++)
                xr[i] = *reinterpret_cast<const float4*>(
                    &x[(size_t)(bm + lrow + 32 * i) * DMODEL + kk + lc4 * 4]);
#pragma unroll
            for (int i = 0; i < 2; i++)
                wr[i] = *reinterpret_cast<const float4*>(
                    &w1[(size_t)(lrow + 32 * i) * DMODEL + kk + lc4 * 4]);
        }

#pragma unroll
        for (int k = 0; k < BK; k++) {
            // 8 consecutive tokens = 4 f32x2 pairs (two conflict-free LDS.128)
            const ulonglong2 xa = *reinterpret_cast<const ulonglong2*>(&xs[k][tg * 8]);
            const ulonglong2 xb = *reinterpret_cast<const ulonglong2*>(&xs[k][tg * 8 + 4]);
            // 8 warp-2-address w values, duplicated into packs (ALU pipe)
            const float4 wa = *reinterpret_cast<const float4*>(&ws[k][e0]);
            const float4 wb = *reinterpret_cast<const float4*>(&ws[k][e0 + 4]);
            unsigned long long wd[8];
            wd[0] = pack2(wa.x, wa.x); wd[1] = pack2(wa.y, wa.y);
            wd[2] = pack2(wa.z, wa.z); wd[3] = pack2(wa.w, wa.w);
            wd[4] = pack2(wb.x, wb.x); wd[5] = pack2(wb.y, wb.y);
            wd[6] = pack2(wb.z, wb.z); wd[7] = pack2(wb.w, wb.w);
#pragma unroll
            for (int e = 0; e < 8; e++) {
                ffma2(acc[0][e], xa.x, wd[e]);
                ffma2(acc[1][e], xa.y, wd[e]);
                ffma2(acc[2][e], xb.x, wd[e]);
                ffma2(acc[3][e], xb.y, wd[e]);
            }
        }
    }

    // ---- epilogue: tanh + store 8 tokens x 8 experts ----
#pragma unroll
    for (int p = 0; p < 4; p++) {
        float lo[8], hi[8];
#pragma unroll
        for (int e = 0; e < 8; e++) unpack2(acc[p][e], lo[e], hi[e]);
        const int t0 = bm + tg * 8 + 2 * p;
        float* d0 = &g_h[(size_t)t0 * NEXP + e0];
        float* d1 = d0 + NEXP;
        *reinterpret_cast<float4*>(d0) =
            make_float4(tanhf(lo[0]), tanhf(lo[1]), tanhf(lo[2]), tanhf(lo[3]));
        *reinterpret_cast<float4*>(d0 + 4) =
            make_float4(tanhf(lo[4]), tanhf(lo[5]), tanhf(lo[6]), tanhf(lo[7]));
        *reinterpret_cast<float4*>(d1) =
            make_float4(tanhf(hi[0]), tanhf(hi[1]), tanhf(hi[2]), tanhf(hi[3]));
        *reinterpret_cast<float4*>(d1 + 4) =
            make_float4(tanhf(hi[4]), tanhf(hi[5]), tanhf(hi[6]), tanhf(hi[7]));
    }
}

// ============================================================================
// Kernel B: logits = h @ w2^T; softmax; argmax(logits+noise); near-tie tokens
// flagged for fp64 rescue; deterministic block partials (no float atomics).
// ============================================================================
__global__ void __launch_bounds__(256)
gate_kernel(const float* __restrict__ w2, const float* __restrict__ noise,
            float* __restrict__ out) {
    __shared__ float w2s[NEXP][NEXP];
    __shared__ float s_imp[8][NEXP];
    __shared__ int   s_load[NEXP];

    const int tid  = threadIdx.x;
    const int warp = tid >> 5;

    for (int i = tid; i < NEXP * NEXP; i += 256) w2s[i >> 6][i & 63] = w2[i];
    if (tid < NEXP) s_load[tid] = 0;
    __syncthreads();

    const int t = blockIdx.x * 256 + tid;

    float l[NEXP];
#pragma unroll
    for (int e = 0; e < NEXP; e++) l[e] = 0.f;

    const float4* hrow = reinterpret_cast<const float4*>(&g_h[(size_t)t * NEXP]);
#pragma unroll 2
    for (int j4 = 0; j4 < 16; j4++) {
        float4 hv = hrow[j4];
#pragma unroll
        for (int e = 0; e < NEXP; e++) {
            l[e] += hv.x * w2s[e][4 * j4 + 0] + hv.y * w2s[e][4 * j4 + 1] +
                    hv.z * w2s[e][4 * j4 + 2] + hv.w * w2s[e][4 * j4 + 3];
        }
    }

    float maxl = l[0];
#pragma unroll
    for (int e = 1; e < NEXP; e++) maxl = fmaxf(maxl, l[e]);

    // argmax of logits + gumbel noise, tracking top-2 margin for rescue
    const float4* nrow = reinterpret_cast<const float4*>(&noise[(size_t)t * NEXP]);
    float best = -3.402823466e38f, second = -3.402823466e38f;
    int   bi   = 0;
#pragma unroll
    for (int e4 = 0; e4 < 16; e4++) {
        float4 nv = nrow[e4];
        float v;
#define STEP(COMP, OFF)                                                        \
        v = l[4 * e4 + OFF] + nv.COMP;                                         \
        if (v > best) { second = best; best = v; bi = 4 * e4 + OFF; }          \
        else if (v > second) { second = v; }
        STEP(x, 0) STEP(y, 1) STEP(z, 2) STEP(w, 3)
#undef STEP
    }
    if (best - second < EPS_MARGIN) {
        int idx = atomicAdd(&g_rescue_cnt, 1);
        if (idx < MAXR) g_rescue_list[idx] = t;
    }

    float Z = 0.f;
#pragma unroll
    for (int e = 0; e < NEXP; e++) Z += expf(l[e] - maxl);
    const float inv = 1.0f / Z;

#pragma unroll
    for (int e = 0; e < NEXP; e++) {
        float v = expf(l[e] - maxl) * inv;
        v += __shfl_xor_sync(0xffffffffu, v, 16);
        v += __shfl_xor_sync(0xffffffffu, v, 8);
        v += __shfl_xor_sync(0xffffffffu, v, 4);
        v += __shfl_xor_sync(0xffffffffu, v, 2);
        v += __shfl_xor_sync(0xffffffffu, v, 1);
        if ((tid & 31) == 0) s_imp[warp][e] = v;
    }

    atomicAdd(&s_load[bi], 1);   // integer atomics: deterministic

    out[t]          = (float)bi;
    out[TOKENS + t] = best;

    __syncthreads();
    if (tid < NEXP) {
        float s = 0.f;
#pragma unroll
        for (int w = 0; w < 8; w++) s += s_imp[w][tid];
        g_imp[blockIdx.x * NEXP + tid]  = s;
        g_load[blockIdx.x * NEXP + tid] = s_load[tid];
    }
}

// ============================================================================
// Rescue: recompute flagged tokens' gate in fp64 straight from inputs,
// patch indices/scores, accumulate integer load deltas. Deterministic.
// ============================================================================
__global__ void __launch_bounds__(256)
rescue_kernel(const float* __restrict__ x, const float* __restrict__ w1,
              const float* __restrict__ w2, const float* __restrict__ noise,
              float* __restrict__ out) {
    int cnt = g_rescue_cnt;
    if (cnt > MAXR) cnt = MAXR;
    if ((int)blockIdx.x >= cnt) return;
    const int t   = g_rescue_list[blockIdx.x];
    const int tid = threadIdx.x;
    const int j   = tid >> 2;     // expert for layer-1 row
    const int q   = tid & 3;      // k-quarter

    __shared__ double pz[NEXP][4];
    __shared__ double hs[NEXP];
    __shared__ double lv[NEXP];

    const float* xr = x + (size_t)t * DMODEL;
    const float* wr = w1 + (size_t)j * DMODEL;
    double partial = 0.0;
    const int k0 = q * (DMODEL / 4);
#pragma unroll 4
    for (int k = k0; k < k0 + DMODEL / 4; k++)
        partial += (double)xr[k] * (double)wr[k];
    pz[j][q] = partial;
    __syncthreads();

    if (q == 0) {
        double z = ((pz[j][0] + pz[j][1]) + pz[j][2]) + pz[j][3];
        hs[j] = tanh(z);
    }
    __syncthreads();

    if (tid < NEXP) {
        double s = 0.0;
        for (int jj = 0; jj < NEXP; jj++) s += hs[jj] * (double)w2[tid * NEXP + jj];
        lv[tid] = s + (double)noise[(size_t)t * NEXP + tid];
    }
    __syncthreads();

    if (tid == 0) {
        double bv = lv[0];
        int bi = 0;
        for (int e = 1; e < NEXP; e++)
            if (lv[e] > bv) { bv = lv[e]; bi = e; }
        const int old = (int)out[t];
        if (old != bi) {
            atomicAdd(&g_load_delta[old], -1);
            atomicAdd(&g_load_delta[bi], 1);
            out[t] = (float)bi;
        }
        out[TOKENS + t] = (float)bv;
    }
}

// ============================================================================
// Kernel C: finalize (deterministic fixed-order reductions + rescue deltas)
// ============================================================================
__global__ void finalize_kernel(float* __restrict__ out) {
    __shared__ float red[NEXP];
    const int e = threadIdx.x;

    float s  = 0.f;
    int   ld = g_load_delta[e];
    for (int b = 0; b < NBLK_B; b++) {
        s  += g_imp[b * NEXP + e];
        ld += g_load[b * NEXP + e];
    }
    const float imp_mean  = s * (1.0f / TOKENS);
    const float load_mean = (float)ld * (1.0f / TOKENS);

    out[2 * TOKENS + 1 + e]        = load_mean;
    out[2 * TOKENS + 1 + NEXP + e] = imp_mean;

    red[e] = imp_mean * load_mean;
    __syncthreads();
    if (e == 0) {
        float a = 0.f;
        for (int i = 0; i < NEXP; i++) a += red[i];
        out[2 * TOKENS] = (float)NEXP * a * 0.1f;
    }
}

extern "C" void kernel_launch(void* const* d_in, const int* in_sizes, int n_in,
                              void* d_out, int out_size) {
    const float* x     = (const float*)d_in[0];
    const float* w1    = (const float*)d_in[1];
    const float* w2    = (const float*)d_in[2];
    const float* noise = (const float*)d_in[3];
    float* out = (float*)d_out;

    gemm1_tanh<<<TOKENS / BM, 128>>>(x, w1);
    gate_kernel<<<NBLK_B, 256>>>(w2, noise, out);
    rescue_kernel<<<MAXR, 256>>>(x, w1, w2, noise, out);
    finalize_kernel<<<1, NEXP>>>(out);
}